// round 2
// baseline (speedup 1.0000x reference)
#include <cuda_runtime.h>
#include <math.h>
#include <stdint.h>

#define BATCH 16
#define SEQ   4096
#define DIM   256
#define FEPS  1e-6f

// ---------------- scratch (device globals; allocation-free rule) ----------------
__device__ __align__(256) float g_phi_q[BATCH * SEQ * DIM];   // 64 MB
__device__ __align__(256) float g_phi_k[BATCH * SEQ * DIM];   // 64 MB
__device__ __align__(256) float g_Vb[BATCH * SEQ * DIM];      // 64 MB
__device__ __align__(256) float g_KV[BATCH * DIM * DIM];      // 4 MB
__device__ __align__(256) float g_colsum[BATCH * DIM];
__device__ __align__(256) float g_rowfac[BATCH * SEQ];
__device__ __align__(256) float g_pm[BATCH * 32 * DIM];
__device__ __align__(256) float g_pl[BATCH * 32 * DIM];
__device__ __align__(256) float g_m[BATCH * DIM];
__device__ __align__(256) float g_il[BATCH * DIM];

__device__ __forceinline__ float fast_sigmoid(float x) {
    return __fdividef(1.f, 1.f + __expf(-x));
}

// ---------------- zero init for atomics targets ----------------
__global__ void zero_kernel() {
    unsigned i = blockIdx.x * blockDim.x + threadIdx.x;
    if (i < BATCH * DIM * DIM) g_KV[i] = 0.f;
    if (i < BATCH * DIM) g_colsum[i] = 0.f;
}

// ---------------- 128x128x16 SGEMM, 8x8 per thread ----------------
// MODE 0: C = sigmoid(A@B + bias)        (aux = bias[DIM])
// MODE 1: C = rowfac[row] * (A@B)        (aux = rowfac, per-z stride auxStrideZ)
template <int MODE>
__global__ __launch_bounds__(256) void gemm128_kernel(
    const float* __restrict__ A, const float* __restrict__ B,
    const float* __restrict__ aux, float* __restrict__ C,
    size_t strideAz, size_t strideBz, size_t strideCz, int auxStrideZ)
{
    const int K = DIM, LDB = DIM, LDC = DIM;
    int z = blockIdx.z;
    const float* Ab = A + (size_t)z * strideAz + (size_t)blockIdx.x * 128 * K;
    const float* Bb = B + (size_t)z * strideBz + blockIdx.y * 128;
    float* Cb = C + (size_t)z * strideCz;

    __shared__ float As[16][132];   // A transposed tile, padded
    __shared__ float Bs[16][128];

    int tid = threadIdx.x;
    int tx = tid & 15, ty = tid >> 4;

    float acc[8][8] = {};

    for (int kt = 0; kt < K; kt += 16) {
#pragma unroll
        for (int i = 0; i < 2; i++) {
            int lin = tid + i * 256;
            // A: 128 rows x 16 k  (512 float4)
            int rowA = lin >> 2, c4 = lin & 3;
            float4 va = *(const float4*)(Ab + (size_t)rowA * K + kt + c4 * 4);
            As[c4 * 4 + 0][rowA] = va.x;
            As[c4 * 4 + 1][rowA] = va.y;
            As[c4 * 4 + 2][rowA] = va.z;
            As[c4 * 4 + 3][rowA] = va.w;
            // B: 16 k x 128 cols (512 float4)
            int rowB = lin >> 5, cB = (lin & 31) * 4;
            *(float4*)&Bs[rowB][cB] =
                *(const float4*)(Bb + (size_t)(kt + rowB) * LDB + cB);
        }
        __syncthreads();
#pragma unroll
        for (int k = 0; k < 16; k++) {
            float4 a0 = *(float4*)&As[k][ty * 8];
            float4 a1 = *(float4*)&As[k][ty * 8 + 4];
            float4 b0 = *(float4*)&Bs[k][tx * 8];
            float4 b1 = *(float4*)&Bs[k][tx * 8 + 4];
            float a[8] = {a0.x, a0.y, a0.z, a0.w, a1.x, a1.y, a1.z, a1.w};
            float b[8] = {b0.x, b0.y, b0.z, b0.w, b1.x, b1.y, b1.z, b1.w};
#pragma unroll
            for (int i = 0; i < 8; i++)
#pragma unroll
                for (int j = 0; j < 8; j++)
                    acc[i][j] = fmaf(a[i], b[j], acc[i][j]);
        }
        __syncthreads();
    }

    int col0 = blockIdx.y * 128 + tx * 8;
    float4 bias0, bias1;
    if (MODE == 0) {
        bias0 = *(const float4*)&aux[col0];
        bias1 = *(const float4*)&aux[col0 + 4];
    }
#pragma unroll
    for (int i = 0; i < 8; i++) {
        int row = blockIdx.x * 128 + ty * 8 + i;
        float4 o0, o1;
        if (MODE == 0) {
            o0.x = fast_sigmoid(acc[i][0] + bias0.x);
            o0.y = fast_sigmoid(acc[i][1] + bias0.y);
            o0.z = fast_sigmoid(acc[i][2] + bias0.z);
            o0.w = fast_sigmoid(acc[i][3] + bias0.w);
            o1.x = fast_sigmoid(acc[i][4] + bias1.x);
            o1.y = fast_sigmoid(acc[i][5] + bias1.y);
            o1.z = fast_sigmoid(acc[i][6] + bias1.z);
            o1.w = fast_sigmoid(acc[i][7] + bias1.w);
        } else {
            float f = aux[(size_t)z * auxStrideZ + row];
            o0.x = f * acc[i][0]; o0.y = f * acc[i][1];
            o0.z = f * acc[i][2]; o0.w = f * acc[i][3];
            o1.x = f * acc[i][4]; o1.y = f * acc[i][5];
            o1.z = f * acc[i][6]; o1.w = f * acc[i][7];
        }
        *(float4*)(Cb + (size_t)row * LDC + col0) = o0;
        *(float4*)(Cb + (size_t)row * LDC + col0 + 4) = o1;
    }
}

// ---------------- rowsum of phi_q -> combined gate/normalizer factor ----------------
__global__ void rowfac_kernel() {
    int warp = threadIdx.x >> 5, lane = threadIdx.x & 31;
    size_t row = (size_t)blockIdx.x * 8 + warp;   // < BATCH*SEQ
    const float* p = g_phi_q + row * DIM;
    float4 v0 = *(const float4*)&p[lane * 4];
    float4 v1 = *(const float4*)&p[128 + lane * 4];
    float s = v0.x + v0.y + v0.z + v0.w + v1.x + v1.y + v1.z + v1.w;
#pragma unroll
    for (int off = 16; off; off >>= 1) s += __shfl_xor_sync(0xffffffffu, s, off);
    if (lane == 0) {
        g_rowfac[row] = fast_sigmoid(s) * __fdividef(1.f, s + FEPS);
    }
}

// ---------------- column sums of phi_k over sequence ----------------
__global__ void colsum_kernel() {
    int b = blockIdx.x >> 5, ns = blockIdx.x & 31;
    const int CH = SEQ / 32;   // 128
    const float* p = g_phi_k + ((size_t)b * SEQ + (size_t)ns * CH) * DIM + threadIdx.x;
    float s = 0.f;
#pragma unroll 4
    for (int n = 0; n < CH; n++) s += p[(size_t)n * DIM];
    atomicAdd(&g_colsum[b * DIM + threadIdx.x], s);
}

// ---------------- per-column online softmax partials over sequence ----------------
__global__ void stats_kernel(const float* __restrict__ V) {
    int b = blockIdx.x >> 5, ns = blockIdx.x & 31;
    const int CH = SEQ / 32;
    int d = threadIdx.x;
    float inv = __fdividef(1.f, g_colsum[b * DIM + d] + FEPS);
    size_t base = ((size_t)b * SEQ + (size_t)ns * CH) * DIM + d;
    float m = -1e30f, l = 0.f;
    for (int n = 0; n < CH; n++) {
        float s = g_phi_k[base + (size_t)n * DIM] * inv * V[base + (size_t)n * DIM];
        float nm = fmaxf(m, s);
        l = l * __expf(m - nm) + __expf(s - nm);
        m = nm;
    }
    g_pm[(b * 32 + ns) * DIM + d] = m;
    g_pl[(b * 32 + ns) * DIM + d] = l;
}

__global__ void merge_kernel() {
    int b = blockIdx.x, d = threadIdx.x;
    float m = -1e30f;
#pragma unroll
    for (int c = 0; c < 32; c++) m = fmaxf(m, g_pm[(b * 32 + c) * DIM + d]);
    float l = 0.f;
#pragma unroll
    for (int c = 0; c < 32; c++)
        l += g_pl[(b * 32 + c) * DIM + d] * __expf(g_pm[(b * 32 + c) * DIM + d] - m);
    g_m[b * DIM + d] = m;
    g_il[b * DIM + d] = __fdividef(1.f, l);
}

// ---------------- V_b = softmax(O*V, axis=seq) ----------------
__global__ void vb_kernel(const float* __restrict__ V) {
    size_t idx = ((size_t)blockIdx.x * blockDim.x + threadIdx.x) * 4;
    int d = (int)(idx & (DIM - 1));
    int b = (int)(idx >> 20);                  // SEQ*DIM = 2^20
    int bd = b * DIM + d;
    float4 pk = *(const float4*)&g_phi_k[idx];
    float4 v  = *(const float4*)&V[idx];
    float4 cs = *(const float4*)&g_colsum[bd];
    float4 mm = *(const float4*)&g_m[bd];
    float4 il = *(const float4*)&g_il[bd];
    float4 o;
    o.x = __expf(pk.x * __fdividef(1.f, cs.x + FEPS) * v.x - mm.x) * il.x;
    o.y = __expf(pk.y * __fdividef(1.f, cs.y + FEPS) * v.y - mm.y) * il.y;
    o.z = __expf(pk.z * __fdividef(1.f, cs.z + FEPS) * v.z - mm.z) * il.z;
    o.w = __expf(pk.w * __fdividef(1.f, cs.w + FEPS) * v.w - mm.w) * il.w;
    *(float4*)&g_Vb[idx] = o;
}

// ---------------- KV[b] = phi_k[b]^T @ Vb[b], split-N with atomics ----------------
#define NSPLIT_KV 8
__global__ __launch_bounds__(256) void kv_kernel() {
    int b = blockIdx.z / NSPLIT_KV, ns = blockIdx.z % NSPLIT_KV;
    const int CH = SEQ / NSPLIT_KV;   // 512
    const float* Ab = g_phi_k + ((size_t)b * SEQ + (size_t)ns * CH) * DIM + blockIdx.x * 128;
    const float* Bb = g_Vb    + ((size_t)b * SEQ + (size_t)ns * CH) * DIM + blockIdx.y * 128;

    __shared__ float As[16][128];
    __shared__ float Bs[16][128];
    int tid = threadIdx.x;
    int tx = tid & 15, ty = tid >> 4;
    float acc[8][8] = {};

    for (int n0 = 0; n0 < CH; n0 += 16) {
#pragma unroll
        for (int i = 0; i < 2; i++) {
            int lin = tid + i * 256;
            int r = lin >> 5, c = (lin & 31) * 4;
            *(float4*)&As[r][c] = *(const float4*)(Ab + (size_t)(n0 + r) * DIM + c);
            *(float4*)&Bs[r][c] = *(const float4*)(Bb + (size_t)(n0 + r) * DIM + c);
        }
        __syncthreads();
#pragma unroll
        for (int k = 0; k < 16; k++) {
            float4 a0 = *(float4*)&As[k][ty * 8];
            float4 a1 = *(float4*)&As[k][ty * 8 + 4];
            float4 b0 = *(float4*)&Bs[k][tx * 8];
            float4 b1 = *(float4*)&Bs[k][tx * 8 + 4];
            float a[8] = {a0.x, a0.y, a0.z, a0.w, a1.x, a1.y, a1.z, a1.w};
            float bb[8] = {b0.x, b0.y, b0.z, b0.w, b1.x, b1.y, b1.z, b1.w};
#pragma unroll
            for (int i = 0; i < 8; i++)
#pragma unroll
                for (int j = 0; j < 8; j++)
                    acc[i][j] = fmaf(a[i], bb[j], acc[i][j]);
        }
        __syncthreads();
    }

    float* Cb = g_KV + (size_t)b * DIM * DIM;
    int d0 = blockIdx.x * 128 + ty * 8;
    int e0 = blockIdx.y * 128 + tx * 8;
#pragma unroll
    for (int i = 0; i < 8; i++)
#pragma unroll
        for (int j = 0; j < 8; j++)
            atomicAdd(&Cb[(size_t)(d0 + i) * DIM + e0 + j], acc[i][j]);
}

// ---------------- launch ----------------
extern "C" void kernel_launch(void* const* d_in, const int* in_sizes, int n_in,
                              void* d_out, int out_size) {
    const float* Q  = (const float*)d_in[0];
    const float* K  = (const float*)d_in[1];
    const float* V  = (const float*)d_in[2];
    const float* Wq = (const float*)d_in[3];
    const float* bq = (const float*)d_in[4];
    const float* Wk = (const float*)d_in[5];
    const float* bk = (const float*)d_in[6];
    float* out = (float*)d_out;

    void *p_phi_q, *p_phi_k, *p_KV, *p_rowfac;
    cudaGetSymbolAddress(&p_phi_q, g_phi_q);
    cudaGetSymbolAddress(&p_phi_k, g_phi_k);
    cudaGetSymbolAddress(&p_KV, g_KV);
    cudaGetSymbolAddress(&p_rowfac, g_rowfac);

    zero_kernel<<<4096, 256>>>();

    // phi_q = sigmoid(Q@Wq + bq), phi_k = sigmoid(K@Wk + bk)   [65536 x 256]
    gemm128_kernel<0><<<dim3(512, 2, 1), 256>>>(Q, Wq, bq, (float*)p_phi_q, 0, 0, 0, 0);
    gemm128_kernel<0><<<dim3(512, 2, 1), 256>>>(K, Wk, bk, (float*)p_phi_k, 0, 0, 0, 0);

    rowfac_kernel<<<BATCH * SEQ / 8, 256>>>();
    colsum_kernel<<<BATCH * 32, 256>>>();
    stats_kernel<<<BATCH * 32, 256>>>(V);
    merge_kernel<<<BATCH, 256>>>();
    vb_kernel<<<BATCH * SEQ * DIM / 4 / 256, 256>>>(V);

    kv_kernel<<<dim3(2, 2, BATCH * NSPLIT_KV), 256>>>();

    // R = rowfac * (phi_q @ KV)   per-batch GEMM [4096x256] @ [256x256]
    gemm128_kernel<1><<<dim3(SEQ / 128, 2, BATCH), 256>>>(
        (const float*)p_phi_q, (const float*)p_KV, (const float*)p_rowfac, out,
        (size_t)SEQ * DIM, (size_t)DIM * DIM, (size_t)SEQ * DIM, SEQ);
}